// round 4
// baseline (speedup 1.0000x reference)
#include <cuda_runtime.h>
#include <cuda_bf16.h>
#include <cstdint>
#include <math.h>

#define BATCH   16384
#define EMB     128
#define NCAT    26
#define XDIM    512      /* 480 padded to 512 */

typedef __nv_bfloat16 bf16;

// ---------------- scratch (device globals; allocation-free) ----------------
__device__ bf16  g_h1h[BATCH * 512],  g_h1l[BATCH * 512];
__device__ bf16  g_h2h[BATCH * 256],  g_h2l[BATCH * 256];
__device__ float g_bot[BATCH * 128];
__device__ bf16  g_xh [BATCH * XDIM], g_xl [BATCH * XDIM];
__device__ bf16  g_t1h[BATCH * 1024], g_t1l[BATCH * 1024];
__device__ bf16  g_t2h[BATCH * 1024], g_t2l[BATCH * 1024];
__device__ bf16  g_t3h[BATCH * 512],  g_t3l[BATCH * 512];
__device__ float g_t4 [BATCH * 256];
// split weights
__device__ bf16  g_w2h [256 * 512],   g_w2l [256 * 512];
__device__ bf16  g_w3h [128 * 256],   g_w3l [128 * 256];
__device__ bf16  g_tw1h[1024 * XDIM], g_tw1l[1024 * XDIM];   // padded 480->512
__device__ bf16  g_tw2h[1024 * 1024], g_tw2l[1024 * 1024];
__device__ bf16  g_tw3h[512 * 1024],  g_tw3l[512 * 1024];
__device__ bf16  g_tw4h[256 * 512],   g_tw4l[256 * 512];

// ======================= helpers ============================================
__device__ __forceinline__ uint32_t smem_u32(const void* p) {
    uint32_t a;
    asm("{ .reg .u64 t; cvta.to.shared.u64 t, %1; cvt.u32.u64 %0, t; }"
        : "=r"(a) : "l"(p));
    return a;
}

__device__ __forceinline__ void split2(float a, float b, uint32_t& hi, uint32_t& lo) {
    __nv_bfloat162 h = __floats2bfloat162_rn(a, b);
    float ha = __bfloat162float(h.x), hb = __bfloat162float(h.y);
    __nv_bfloat162 l = __floats2bfloat162_rn(a - ha, b - hb);
    hi = *reinterpret_cast<uint32_t*>(&h);
    lo = *reinterpret_cast<uint32_t*>(&l);
}

#define LDSM4(r0, r1, r2, r3, addr) \
    asm volatile("ldmatrix.sync.aligned.m8n8.x4.shared.b16 {%0,%1,%2,%3}, [%4];" \
        : "=r"(r0), "=r"(r1), "=r"(r2), "=r"(r3) : "r"(addr))

#define MMA_BF16(c, a, b0, b1) \
    asm volatile("mma.sync.aligned.m16n8k16.row.col.f32.bf16.bf16.f32 " \
        "{%0,%1,%2,%3}, {%4,%5,%6,%7}, {%8,%9}, {%0,%1,%2,%3};" \
        : "+f"((c)[0]), "+f"((c)[1]), "+f"((c)[2]), "+f"((c)[3]) \
        : "r"((a)[0]), "r"((a)[1]), "r"((a)[2]), "r"((a)[3]), "r"(b0), "r"(b1))

#define CP16(dst, src) \
    asm volatile("cp.async.cg.shared.global [%0], [%1], 16;" :: "r"(dst), "l"(src))
#define CP_COMMIT() asm volatile("cp.async.commit_group;" ::: "memory")
#define CP_WAIT1()  asm volatile("cp.async.wait_group 1;" ::: "memory")
#define CP_WAIT0()  asm volatile("cp.async.wait_group 0;" ::: "memory")

// ============ tensor-core GEMM ==============================================
// C = relu?(A @ W^T + b). A,W given pre-split as bf16 hi/lo [M,K],[N,K].
// Outputs any of: Cf (fp32), Ch/Cl (bf16 hi/lo split, for next layer).
// 128x128 CTA tile, 8 warps (2x4 of 64x32), K-chunk 32, cp.async double buffer.
// smem per buffer: Ah,Al,Wh,Wl each 8KB laid out as 64 contiguous 8x8 bf16
// matrices (128B), mat idx = (row>>3)*4 + koct. Buffers at 0 / 32768;
// bias at 65536. Total 66048 B dynamic.
#define GEMM_SMEM 66048

__global__ __launch_bounds__(256, 2) void gemm_tc(
    const bf16* __restrict__ Ah, const bf16* __restrict__ Al,
    const bf16* __restrict__ Wh, const bf16* __restrict__ Wl,
    const float* __restrict__ bias,
    float* __restrict__ Cf, bf16* __restrict__ Ch, bf16* __restrict__ Cl,
    int K, int N, int relu)
{
    extern __shared__ unsigned char smem[];
    const uint32_t sb = smem_u32(smem);
    const int tid    = threadIdx.x;
    const int lane   = tid & 31;
    const int w      = tid >> 5;
    const int warp_m = w >> 2;
    const int warp_n = w & 3;
    const int row0   = blockIdx.y * 128;
    const int col0   = blockIdx.x * 128;

    float* sbias = (float*)(smem + 65536);
    if (tid < 128) sbias[tid] = bias[col0 + tid];

    const bf16* Abh = Ah + (size_t)row0 * K;
    const bf16* Abl = Al + (size_t)row0 * K;
    const bf16* Wbh = Wh + (size_t)col0 * K;
    const bf16* Wbl = Wl + (size_t)col0 * K;

    // cp.async mapping: thread -> (row, 2 segs of 8 bf16)
    const int crow  = tid >> 1;
    const int cseg0 = (tid & 1) * 2;
    const uint32_t soffA = (uint32_t)(((crow >> 3) * 4) * 128 + (crow & 7) * 16);

    const int nk = K >> 5;

    // prologue: issue chunks 0 and 1
    #pragma unroll
    for (int pc = 0; pc < 2; pc++) {
        if (pc < nk) {
            const uint32_t bufb = sb + (uint32_t)pc * 32768;
            #pragma unroll
            for (int s = 0; s < 2; s++) {
                const int seg = cseg0 + s;
                const uint32_t so = bufb + soffA + (uint32_t)seg * 128;
                const size_t  go = (size_t)crow * K + pc * 32 + seg * 8;
                CP16(so,          Abh + go);
                CP16(so + 8192,   Abl + go);
                CP16(so + 16384,  Wbh + go);
                CP16(so + 24576,  Wbl + go);
            }
            CP_COMMIT();
        }
    }

    // ldmatrix lane offsets
    const int g  = lane >> 3;
    const int lr = lane & 7;
    const uint32_t laneA = (uint32_t)((g & 1) * 512 + (g >> 1) * 128 + lr * 16);
    const uint32_t laneB = (uint32_t)((g & 1) * 128 + (g >> 1) * 512 + lr * 16);

    float acc[4][4][4];
    #pragma unroll
    for (int i = 0; i < 4; i++)
        #pragma unroll
        for (int j = 0; j < 4; j++)
            #pragma unroll
            for (int e = 0; e < 4; e++) acc[i][j][e] = 0.0f;

    for (int ck = 0; ck < nk; ck++) {
        if (ck + 1 < nk) CP_WAIT1(); else CP_WAIT0();
        __syncthreads();
        const uint32_t bufb = sb + (uint32_t)(ck & 1) * 32768;

        #pragma unroll
        for (int kk = 0; kk < 2; kk++) {
            uint32_t ah[4][4], al[4][4], bh[4][2], bl[4][2];
            #pragma unroll
            for (int mt = 0; mt < 4; mt++) {
                const uint32_t ta = bufb
                    + (uint32_t)(((warp_m * 8 + mt * 2) * 4 + kk * 2) * 128) + laneA;
                LDSM4(ah[mt][0], ah[mt][1], ah[mt][2], ah[mt][3], ta);
                LDSM4(al[mt][0], al[mt][1], al[mt][2], al[mt][3], ta + 8192);
            }
            #pragma unroll
            for (int np = 0; np < 2; np++) {
                const uint32_t tb = bufb + 16384
                    + (uint32_t)(((warp_n * 4 + np * 2) * 4 + kk * 2) * 128) + laneB;
                uint32_t r0, r1, r2, r3;
                LDSM4(r0, r1, r2, r3, tb);
                bh[np*2][0] = r0; bh[np*2][1] = r1;
                bh[np*2+1][0] = r2; bh[np*2+1][1] = r3;
                LDSM4(r0, r1, r2, r3, tb + 8192);
                bl[np*2][0] = r0; bl[np*2][1] = r1;
                bl[np*2+1][0] = r2; bl[np*2+1][1] = r3;
            }
            #pragma unroll
            for (int mt = 0; mt < 4; mt++)
                #pragma unroll
                for (int nt = 0; nt < 4; nt++) {
                    MMA_BF16(acc[mt][nt], ah[mt], bh[nt][0], bh[nt][1]);
                    MMA_BF16(acc[mt][nt], ah[mt], bl[nt][0], bl[nt][1]);
                    MMA_BF16(acc[mt][nt], al[mt], bh[nt][0], bh[nt][1]);
                }
        }
        __syncthreads();

        if (ck + 2 < nk) {
            const uint32_t bufb2 = sb + (uint32_t)(ck & 1) * 32768;
            #pragma unroll
            for (int s = 0; s < 2; s++) {
                const int seg = cseg0 + s;
                const uint32_t so = bufb2 + soffA + (uint32_t)seg * 128;
                const size_t  go = (size_t)crow * K + (ck + 2) * 32 + seg * 8;
                CP16(so,          Abh + go);
                CP16(so + 8192,   Abl + go);
                CP16(so + 16384,  Wbh + go);
                CP16(so + 24576,  Wbl + go);
            }
            CP_COMMIT();
        }
    }

    // ---- epilogue: bias + relu, fp32 and/or bf16 hi/lo stores ----
    const int q  = lane >> 2;
    const int tq = lane & 3;
    #pragma unroll
    for (int mt = 0; mt < 4; mt++) {
        const int r0g = row0 + warp_m * 64 + mt * 16 + q;
        #pragma unroll
        for (int nt = 0; nt < 4; nt++) {
            const int cl = warp_n * 32 + nt * 8 + tq * 2;
            const float bx = sbias[cl], by = sbias[cl + 1];
            float v0 = acc[mt][nt][0] + bx, v1 = acc[mt][nt][1] + by;
            float v2 = acc[mt][nt][2] + bx, v3 = acc[mt][nt][3] + by;
            if (relu) {
                v0 = fmaxf(v0, 0.0f); v1 = fmaxf(v1, 0.0f);
                v2 = fmaxf(v2, 0.0f); v3 = fmaxf(v3, 0.0f);
            }
            const size_t o0 = (size_t)r0g * N + col0 + cl;
            const size_t o1 = (size_t)(r0g + 8) * N + col0 + cl;
            if (Cf) {
                *(float2*)(Cf + o0) = make_float2(v0, v1);
                *(float2*)(Cf + o1) = make_float2(v2, v3);
            }
            if (Ch) {
                uint32_t h01, l01, h23, l23;
                split2(v0, v1, h01, l01);
                split2(v2, v3, h23, l23);
                *(uint32_t*)(Ch + o0) = h01;
                *(uint32_t*)(Cl + o0) = l01;
                *(uint32_t*)(Ch + o1) = h23;
                *(uint32_t*)(Cl + o1) = l23;
            }
        }
    }
}

// ---------------- bottom layer 1: [B,13] -> [B,512] bf16 hi/lo, relu -------
__global__ __launch_bounds__(256) void bottom1_kernel(
    const float* __restrict__ X, const float* __restrict__ W,
    const float* __restrict__ bias)
{
    __shared__ float ws[512 * 13];
    __shared__ float bs[512];
    __shared__ float xs[32 * 13];
    const int tid  = threadIdx.x;
    const int row0 = blockIdx.x * 32;

    for (int i = tid; i < 512 * 13; i += 256) ws[i] = W[i];
    for (int i = tid; i < 512;      i += 256) bs[i] = bias[i];
    for (int i = tid; i < 32 * 13;  i += 256) xs[i] = X[row0 * 13 + i];
    __syncthreads();

    for (int o = tid; o < 32 * 512; o += 256) {
        const int col = o & 511;
        const int row = o >> 9;
        float acc = bs[col];
        #pragma unroll
        for (int k = 0; k < 13; k++)
            acc = fmaf(xs[row * 13 + k], ws[col * 13 + k], acc);
        acc = fmaxf(acc, 0.0f);
        bf16 h = __float2bfloat16(acc);
        const size_t oi = (size_t)(row0 + row) * 512 + col;
        g_h1h[oi] = h;
        g_h1l[oi] = __float2bfloat16(acc - __bfloat162float(h));
    }
}

// ---------------- gather + pairwise interactions ---------------------------
// warp per sample; smem 28 rows x 32 float4, XOR-swizzled. Writes x hi/lo bf16.
#define ISMEM (4 * 28 * 32 * 16)
__global__ __launch_bounds__(128) void interact_kernel(
    const int* __restrict__ cat, const float* __restrict__ emb)
{
    extern __shared__ float4 fsm[];
    const int warp = threadIdx.x >> 5;
    const int lane = threadIdx.x & 31;
    const int b    = blockIdx.x * 4 + warp;
    float4* F = fsm + warp * (28 * 32);

    // gather indices first (all in flight), then rows (all in flight)
    int idxs[NCAT];
    #pragma unroll
    for (int t = 0; t < NCAT; t++) idxs[t] = cat[t * BATCH + b];

    float4 bv = ((const float4*)(g_bot + (size_t)b * EMB))[lane];
    F[lane] = bv;
    #pragma unroll
    for (int t = 0; t < NCAT; t++) {
        const int r = t + 1;
        F[r * 32 + (lane ^ ((r >> 2) & 7))] =
            ((const float4*)(emb + ((size_t)t * 100000 + idxs[t]) * EMB))[lane];
    }
    F[27 * 32 + (lane ^ 6)] = make_float4(0.f, 0.f, 0.f, 0.f);
    __syncwarp();

    bf16* xh = g_xh + (size_t)b * XDIM;
    bf16* xl = g_xl + (size_t)b * XDIM;

    // bottom -> x[0:128] (split), zero x[479:512]
    {
        uint32_t h0, l0, h1, l1;
        split2(bv.x, bv.y, h0, l0);
        split2(bv.z, bv.w, h1, l1);
        *(uint2*)(xh + lane * 4) = make_uint2(h0, h1);
        *(uint2*)(xl + lane * 4) = make_uint2(l0, l1);
    }
    const bf16 z = __float2bfloat16(0.0f);
    xh[480 + lane] = z; xl[480 + lane] = z;
    if (lane == 0) { xh[479] = z; xl[479] = z; }

    if (lane < 28) {
        int t = lane, R = 0;
        while (t >= R + 1) { t -= R + 1; R++; }
        const int C = t;
        const int sR = R & 7, sC = C & 7;

        float a[4][4];
        #pragma unroll
        for (int i = 0; i < 4; i++)
            #pragma unroll
            for (int j = 0; j < 4; j++) a[i][j] = 0.0f;

        #pragma unroll 4
        for (int d4 = 0; d4 < 32; d4++) {
            float4 fr[4], fc[4];
            #pragma unroll
            for (int i = 0; i < 4; i++)
                fr[i] = F[(4 * R + i) * 32 + (d4 ^ sR)];
            #pragma unroll
            for (int j = 0; j < 4; j++)
                fc[j] = F[(4 * C + j) * 32 + (d4 ^ sC)];
            #pragma unroll
            for (int i = 0; i < 4; i++)
                #pragma unroll
                for (int j = 0; j < 4; j++) {
                    a[i][j] = fmaf(fr[i].x, fc[j].x, a[i][j]);
                    a[i][j] = fmaf(fr[i].y, fc[j].y, a[i][j]);
                    a[i][j] = fmaf(fr[i].z, fc[j].z, a[i][j]);
                    a[i][j] = fmaf(fr[i].w, fc[j].w, a[i][j]);
                }
        }

        #pragma unroll
        for (int i = 0; i < 4; i++) {
            const int r = 4 * R + i;
            #pragma unroll
            for (int j = 0; j < 4; j++) {
                const int c = 4 * C + j;
                if (r < 27 && c < r) {
                    const float v = a[i][j];
                    const bf16 h = __float2bfloat16(v);
                    const int off = EMB + r * (r - 1) / 2 + c;
                    xh[off] = h;
                    xl[off] = __float2bfloat16(v - __bfloat162float(h));
                }
            }
        }
    }
}

// ---------------- weight prep: split fp32 -> bf16 hi/lo --------------------
__global__ __launch_bounds__(256) void split_w_kernel(
    const float* __restrict__ W, bf16* __restrict__ Wh, bf16* __restrict__ Wl,
    int n)
{
    const int i = blockIdx.x * 256 + threadIdx.x;
    if (i >= n) return;
    const float v = W[i];
    const bf16 h = __float2bfloat16(v);
    Wh[i] = h;
    Wl[i] = __float2bfloat16(v - __bfloat162float(h));
}

// tw1 [1024,480] -> padded [1024,512] hi/lo
__global__ __launch_bounds__(256) void pad_split_w1_kernel(const float* __restrict__ tw1)
{
    const int i = blockIdx.x * 256 + threadIdx.x;     // over 1024*512
    const int r = i >> 9, c = i & 511;
    const float v = (c < 480) ? tw1[r * 480 + c] : 0.0f;
    const bf16 h = __float2bfloat16(v);
    g_tw1h[i] = h;
    g_tw1l[i] = __float2bfloat16(v - __bfloat162float(h));
}

// ---------------- final layer: dot(256) + sigmoid ---------------------------
__global__ __launch_bounds__(256) void final_kernel(
    const float* __restrict__ w5, const float* __restrict__ b5,
    float* __restrict__ out)
{
    const int warp = threadIdx.x >> 5;
    const int lane = threadIdx.x & 31;
    const int b = blockIdx.x * 8 + warp;
    const float* row = g_t4 + (size_t)b * 256;
    float s = 0.0f;
    #pragma unroll
    for (int j = lane; j < 256; j += 32) s = fmaf(row[j], w5[j], s);
    #pragma unroll
    for (int o = 16; o; o >>= 1) s += __shfl_xor_sync(0xffffffffu, s, o);
    if (lane == 0) out[b] = 1.0f / (1.0f + expf(-(s + b5[0])));
}

// ---------------- launcher --------------------------------------------------
template <typename T>
static T* sym_addr(const void* symbol)
{
    void* p = nullptr;
    cudaGetSymbolAddress(&p, symbol);
    return (T*)p;
}

extern "C" void kernel_launch(void* const* d_in, const int* in_sizes, int n_in,
                              void* d_out, int out_size)
{
    const float* Xnum = (const float*)d_in[0];
    const int*   cat  = (const int*)  d_in[1];
    const float* emb  = (const float*)d_in[2];
    const float* bw1  = (const float*)d_in[3];
    const float* bb1  = (const float*)d_in[4];
    const float* bw2  = (const float*)d_in[5];
    const float* bb2  = (const float*)d_in[6];
    const float* bw3  = (const float*)d_in[7];
    const float* bb3  = (const float*)d_in[8];
    const float* tw1  = (const float*)d_in[9];
    const float* tb1  = (const float*)d_in[10];
    const float* tw2  = (const float*)d_in[11];
    const float* tb2  = (const float*)d_in[12];
    const float* tw3  = (const float*)d_in[13];
    const float* tb3  = (const float*)d_in[14];
    const float* tw4  = (const float*)d_in[15];
    const float* tb4  = (const float*)d_in[16];
    const float* tw5  = (const float*)d_in[17];
    const float* tb5  = (const float*)d_in[18];
    float* out = (float*)d_out;

    bf16* h1h = sym_addr<bf16>(g_h1h);   bf16* h1l = sym_addr<bf16>(g_h1l);
    bf16* h2h = sym_addr<bf16>(g_h2h);   bf16* h2l = sym_addr<bf16>(g_h2l);
    float* bot = sym_addr<float>(g_bot);
    bf16* xh  = sym_addr<bf16>(g_xh);    bf16* xl  = sym_addr<bf16>(g_xl);
    bf16* t1h = sym_addr<bf16>(g_t1h);   bf16* t1l = sym_addr<bf16>(g_t1l);
    bf16* t2h = sym_addr<bf16>(g_t2h);   bf16* t2l = sym_addr<bf16>(g_t2l);
    bf16* t3h = sym_addr<bf16>(g_t3h);   bf16* t3l = sym_addr<bf16>(g_t3l);
    float* t4 = sym_addr<float>(g_t4);
    bf16* w2h = sym_addr<bf16>(g_w2h);   bf16* w2l = sym_addr<bf16>(g_w2l);
    bf16* w3h = sym_addr<bf16>(g_w3h);   bf16* w3l = sym_addr<bf16>(g_w3l);
    bf16* u1h = sym_addr<bf16>(g_tw1h);  bf16* u1l = sym_addr<bf16>(g_tw1l);
    bf16* u2h = sym_addr<bf16>(g_tw2h);  bf16* u2l = sym_addr<bf16>(g_tw2l);
    bf16* u3h = sym_addr<bf16>(g_tw3h);  bf16* u3l = sym_addr<bf16>(g_tw3l);
    bf16* u4h = sym_addr<bf16>(g_tw4h);  bf16* u4l = sym_addr<bf16>(g_tw4l);

    static int init_done = 0;
    if (!init_done) {
        cudaFuncSetAttribute(interact_kernel,
                             cudaFuncAttributeMaxDynamicSharedMemorySize, ISMEM);
        cudaFuncSetAttribute(gemm_tc,
                             cudaFuncAttributeMaxDynamicSharedMemorySize, GEMM_SMEM);
        init_done = 1;
    }

    // weight prep (cheap; ~2.4M elems total)
    split_w_kernel<<<(256 * 512 + 255) / 256, 256>>>(bw2, w2h, w2l, 256 * 512);
    split_w_kernel<<<(128 * 256 + 255) / 256, 256>>>(bw3, w3h, w3l, 128 * 256);
    pad_split_w1_kernel<<<(1024 * 512) / 256, 256>>>(tw1);
    split_w_kernel<<<(1024 * 1024 + 255) / 256, 256>>>(tw2, u2h, u2l, 1024 * 1024);
    split_w_kernel<<<(512 * 1024 + 255) / 256, 256>>>(tw3, u3h, u3l, 512 * 1024);
    split_w_kernel<<<(256 * 512 + 255) / 256, 256>>>(tw4, u4h, u4l, 256 * 512);

    // bottom MLP
    bottom1_kernel<<<BATCH / 32, 256>>>(Xnum, bw1, bb1);
    gemm_tc<<<dim3(2, BATCH / 128), 256, GEMM_SMEM>>>(
        h1h, h1l, w2h, w2l, bb2, nullptr, h2h, h2l, 512, 256, 1);
    gemm_tc<<<dim3(1, BATCH / 128), 256, GEMM_SMEM>>>(
        h2h, h2l, w3h, w3l, bb3, bot, nullptr, nullptr, 256, 128, 1);

    // gather + interactions -> x hi/lo [B, 512]
    interact_kernel<<<BATCH / 4, 128, ISMEM>>>(cat, emb);

    // top MLP
    gemm_tc<<<dim3(8, BATCH / 128), 256, GEMM_SMEM>>>(
        xh,  xl,  u1h, u1l, tb1, nullptr, t1h, t1l, 512, 1024, 1);
    gemm_tc<<<dim3(8, BATCH / 128), 256, GEMM_SMEM>>>(
        t1h, t1l, u2h, u2l, tb2, nullptr, t2h, t2l, 1024, 1024, 1);
    gemm_tc<<<dim3(4, BATCH / 128), 256, GEMM_SMEM>>>(
        t2h, t2l, u3h, u3l, tb3, nullptr, t3h, t3l, 1024, 512, 1);
    gemm_tc<<<dim3(2, BATCH / 128), 256, GEMM_SMEM>>>(
        t3h, t3l, u4h, u4l, tb4, t4, nullptr, nullptr, 512, 256, 1);

    // final dot + sigmoid
    final_kernel<<<BATCH / 8, 256>>>(tw5, tb5, out);
}

// round 5
// speedup vs baseline: 1.0405x; 1.0405x over previous
#include <cuda_runtime.h>
#include <cuda_bf16.h>
#include <cstdint>
#include <math.h>

#define BATCH   16384
#define EMB     128
#define NCAT    26
#define XDIM    512      /* 480 padded to 512 */

typedef __nv_bfloat16 bf16;

// ---------------- scratch (device globals; allocation-free) ----------------
__device__ bf16  g_h1h[BATCH * 512],  g_h1l[BATCH * 512];
__device__ bf16  g_h2h[BATCH * 256],  g_h2l[BATCH * 256];
__device__ float g_bot[BATCH * 128];
__device__ bf16  g_xh [BATCH * XDIM], g_xl [BATCH * XDIM];
__device__ bf16  g_t1h[BATCH * 1024], g_t1l[BATCH * 1024];
__device__ bf16  g_t2h[BATCH * 1024], g_t2l[BATCH * 1024];
__device__ bf16  g_t3h[BATCH * 512],  g_t3l[BATCH * 512];
__device__ float g_t4 [BATCH * 256];
// split weights
__device__ bf16  g_w2h [256 * 512],   g_w2l [256 * 512];
__device__ bf16  g_w3h [128 * 256],   g_w3l [128 * 256];
__device__ bf16  g_tw1h[1024 * XDIM], g_tw1l[1024 * XDIM];   // padded 480->512
__device__ bf16  g_tw2h[1024 * 1024], g_tw2l[1024 * 1024];
__device__ bf16  g_tw3h[512 * 1024],  g_tw3l[512 * 1024];
__device__ bf16  g_tw4h[256 * 512],   g_tw4l[256 * 512];

// ======================= helpers ============================================
__device__ __forceinline__ uint32_t smem_u32(const void* p) {
    uint32_t a;
    asm("{ .reg .u64 t; cvta.to.shared.u64 t, %1; cvt.u32.u64 %0, t; }"
        : "=r"(a) : "l"(p));
    return a;
}

__device__ __forceinline__ void split2(float a, float b, uint32_t& hi, uint32_t& lo) {
    __nv_bfloat162 h = __floats2bfloat162_rn(a, b);
    float ha = __bfloat162float(h.x), hb = __bfloat162float(h.y);
    __nv_bfloat162 l = __floats2bfloat162_rn(a - ha, b - hb);
    hi = *reinterpret_cast<uint32_t*>(&h);
    lo = *reinterpret_cast<uint32_t*>(&l);
}

#define LDSM4(r0, r1, r2, r3, addr) \
    asm volatile("ldmatrix.sync.aligned.m8n8.x4.shared.b16 {%0,%1,%2,%3}, [%4];" \
        : "=r"(r0), "=r"(r1), "=r"(r2), "=r"(r3) : "r"(addr))

#define MMA_BF16(c, a, b0, b1) \
    asm volatile("mma.sync.aligned.m16n8k16.row.col.f32.bf16.bf16.f32 " \
        "{%0,%1,%2,%3}, {%4,%5,%6,%7}, {%8,%9}, {%0,%1,%2,%3};" \
        : "+f"((c)[0]), "+f"((c)[1]), "+f"((c)[2]), "+f"((c)[3]) \
        : "r"((a)[0]), "r"((a)[1]), "r"((a)[2]), "r"((a)[3]), "r"(b0), "r"(b1))

#define CP16(dst, src) \
    asm volatile("cp.async.cg.shared.global [%0], [%1], 16;" :: "r"(dst), "l"(src))
#define CP_COMMIT() asm volatile("cp.async.commit_group;" ::: "memory")
#define CP_WAIT2()  asm volatile("cp.async.wait_group 2;" ::: "memory")

// ============ tensor-core GEMM ==============================================
// C = relu?(A @ W^T + b). A,W given pre-split as bf16 hi/lo [M,K],[N,K].
// 128x128 CTA tile, 8 warps (2x4 of 64x32), K-chunk 32, 4-stage cp.async.
// smem per stage (32KB): Ah,Al,Wh,Wl each 8KB as 8x8-matrix-contiguous
// (128B mats, mat idx = (row>>3)*4 + koct). bias at 131072. Total 131584.
#define GEMM_SMEM (4 * 32768 + 512)

__global__ __launch_bounds__(256, 1) void gemm_tc(
    const bf16* __restrict__ Ah, const bf16* __restrict__ Al,
    const bf16* __restrict__ Wh, const bf16* __restrict__ Wl,
    const float* __restrict__ bias,
    float* __restrict__ Cf, bf16* __restrict__ Ch, bf16* __restrict__ Cl,
    int K, int N, int relu)
{
    extern __shared__ unsigned char smem[];
    const uint32_t sb = smem_u32(smem);
    const int tid    = threadIdx.x;
    const int lane   = tid & 31;
    const int w      = tid >> 5;
    const int warp_m = w >> 2;
    const int warp_n = w & 3;
    const int row0   = blockIdx.y * 128;
    const int col0   = blockIdx.x * 128;

    float* sbias = (float*)(smem + 131072);
    if (tid < 128) sbias[tid] = bias[col0 + tid];

    const bf16* Abh = Ah + (size_t)row0 * K;
    const bf16* Abl = Al + (size_t)row0 * K;
    const bf16* Wbh = Wh + (size_t)col0 * K;
    const bf16* Wbl = Wl + (size_t)col0 * K;

    // cp.async mapping: thread -> (row, 2 segs of 8 bf16)
    const int crow  = tid >> 1;
    const int cseg0 = (tid & 1) * 2;
    const uint32_t soffA = (uint32_t)(((crow >> 3) * 4) * 128 + (crow & 7) * 16);

    const int nk = K >> 5;

    // prologue: issue stages 0..2
    #pragma unroll
    for (int pc = 0; pc < 3; pc++) {
        if (pc < nk) {
            const uint32_t bufb = sb + (uint32_t)pc * 32768;
            #pragma unroll
            for (int s = 0; s < 2; s++) {
                const int seg = cseg0 + s;
                const uint32_t so = bufb + soffA + (uint32_t)seg * 128;
                const size_t  go = (size_t)crow * K + pc * 32 + seg * 8;
                CP16(so,          Abh + go);
                CP16(so + 8192,   Abl + go);
                CP16(so + 16384,  Wbh + go);
                CP16(so + 24576,  Wbl + go);
            }
        }
        CP_COMMIT();
    }

    // ldmatrix lane offsets
    const int g  = lane >> 3;
    const int lr = lane & 7;
    const uint32_t laneA = (uint32_t)((g & 1) * 512 + (g >> 1) * 128 + lr * 16);
    const uint32_t laneB = (uint32_t)((g & 1) * 128 + (g >> 1) * 512 + lr * 16);

    float acc[4][4][4];
    #pragma unroll
    for (int i = 0; i < 4; i++)
        #pragma unroll
        for (int j = 0; j < 4; j++)
            #pragma unroll
            for (int e = 0; e < 4; e++) acc[i][j][e] = 0.0f;

    for (int ck = 0; ck < nk; ck++) {
        CP_WAIT2();            // stage ck complete (2 newer may be in flight)
        __syncthreads();       // also: all warps done consuming stage ck-1
        const uint32_t bufb = sb + (uint32_t)(ck & 3) * 32768;

        #pragma unroll
        for (int kk = 0; kk < 2; kk++) {
            const uint32_t koff = (uint32_t)(kk * 2 * 128);
            uint32_t ah[4][4], al[4][4], bh[4][2], bl[4][2];

            // ---- term hh: A-hi x B-hi (16 independent accumulators) ----
            #pragma unroll
            for (int mt = 0; mt < 4; mt++) {
                const uint32_t ta = bufb
                    + (uint32_t)((warp_m * 8 + mt * 2) * 4 * 128) + koff + laneA;
                LDSM4(ah[mt][0], ah[mt][1], ah[mt][2], ah[mt][3], ta);
            }
            #pragma unroll
            for (int np = 0; np < 2; np++) {
                const uint32_t tb = bufb + 16384
                    + (uint32_t)((warp_n * 4 + np * 2) * 4 * 128) + koff + laneB;
                uint32_t r0, r1, r2, r3;
                LDSM4(r0, r1, r2, r3, tb);
                bh[np*2][0] = r0; bh[np*2][1] = r1;
                bh[np*2+1][0] = r2; bh[np*2+1][1] = r3;
            }
            #pragma unroll
            for (int mt = 0; mt < 4; mt++)
                #pragma unroll
                for (int nt = 0; nt < 4; nt++)
                    MMA_BF16(acc[mt][nt], ah[mt], bh[nt][0], bh[nt][1]);

            // ---- term lh: A-lo x B-hi ----
            #pragma unroll
            for (int mt = 0; mt < 4; mt++) {
                const uint32_t ta = bufb + 8192
                    + (uint32_t)((warp_m * 8 + mt * 2) * 4 * 128) + koff + laneA;
                LDSM4(al[mt][0], al[mt][1], al[mt][2], al[mt][3], ta);
            }
            #pragma unroll
            for (int mt = 0; mt < 4; mt++)
                #pragma unroll
                for (int nt = 0; nt < 4; nt++)
                    MMA_BF16(acc[mt][nt], al[mt], bh[nt][0], bh[nt][1]);

            // ---- term hl: A-hi x B-lo ----
            #pragma unroll
            for (int np = 0; np < 2; np++) {
                const uint32_t tb = bufb + 24576
                    + (uint32_t)((warp_n * 4 + np * 2) * 4 * 128) + koff + laneB;
                uint32_t r0, r1, r2, r3;
                LDSM4(r0, r1, r2, r3, tb);
                bl[np*2][0] = r0; bl[np*2][1] = r1;
                bl[np*2+1][0] = r2; bl[np*2+1][1] = r3;
            }
            #pragma unroll
            for (int mt = 0; mt < 4; mt++)
                #pragma unroll
                for (int nt = 0; nt < 4; nt++)
                    MMA_BF16(acc[mt][nt], ah[mt], bl[nt][0], bl[nt][1]);
        }

        // issue stage ck+3 into buffer (ck+3)&3 (freed: consumed at ck-1)
        if (ck + 3 < nk) {
            const uint32_t bufb2 = sb + (uint32_t)((ck + 3) & 3) * 32768;
            #pragma unroll
            for (int s = 0; s < 2; s++) {
                const int seg = cseg0 + s;
                const uint32_t so = bufb2 + soffA + (uint32_t)seg * 128;
                const size_t  go = (size_t)crow * K + (ck + 3) * 32 + seg * 8;
                CP16(so,          Abh + go);
                CP16(so + 8192,   Abl + go);
                CP16(so + 16384,  Wbh + go);
                CP16(so + 24576,  Wbl + go);
            }
        }
        CP_COMMIT();   // unconditional: keeps group accounting exact
    }

    // ---- epilogue: bias + relu, fp32 and/or bf16 hi/lo stores ----
    const int q  = lane >> 2;
    const int tq = lane & 3;
    #pragma unroll
    for (int mt = 0; mt < 4; mt++) {
        const int r0g = row0 + warp_m * 64 + mt * 16 + q;
        #pragma unroll
        for (int nt = 0; nt < 4; nt++) {
            const int cl = warp_n * 32 + nt * 8 + tq * 2;
            const float bx = sbias[cl], by = sbias[cl + 1];
            float v0 = acc[mt][nt][0] + bx, v1 = acc[mt][nt][1] + by;
            float v2 = acc[mt][nt][2] + bx, v3 = acc[mt][nt][3] + by;
            if (relu) {
                v0 = fmaxf(v0, 0.0f); v1 = fmaxf(v1, 0.0f);
                v2 = fmaxf(v2, 0.0f); v3 = fmaxf(v3, 0.0f);
            }
            const size_t o0 = (size_t)r0g * N + col0 + cl;
            const size_t o1 = (size_t)(r0g + 8) * N + col0 + cl;
            if (Cf) {
                *(float2*)(Cf + o0) = make_float2(v0, v1);
                *(float2*)(Cf + o1) = make_float2(v2, v3);
            }
            if (Ch) {
                uint32_t h01, l01, h23, l23;
                split2(v0, v1, h01, l01);
                split2(v2, v3, h23, l23);
                *(uint32_t*)(Ch + o0) = h01;
                *(uint32_t*)(Cl + o0) = l01;
                *(uint32_t*)(Ch + o1) = h23;
                *(uint32_t*)(Cl + o1) = l23;
            }
        }
    }
}

// ---------------- bottom layer 1: [B,13] -> [B,512] bf16 hi/lo, relu -------
__global__ __launch_bounds__(256) void bottom1_kernel(
    const float* __restrict__ X, const float* __restrict__ W,
    const float* __restrict__ bias)
{
    __shared__ float ws[512 * 13];
    __shared__ float bs[512];
    __shared__ float xs[32 * 13];
    const int tid  = threadIdx.x;
    const int row0 = blockIdx.x * 32;

    for (int i = tid; i < 512 * 13; i += 256) ws[i] = W[i];
    for (int i = tid; i < 512;      i += 256) bs[i] = bias[i];
    for (int i = tid; i < 32 * 13;  i += 256) xs[i] = X[row0 * 13 + i];
    __syncthreads();

    for (int o = tid; o < 32 * 512; o += 256) {
        const int col = o & 511;
        const int row = o >> 9;
        float acc = bs[col];
        #pragma unroll
        for (int k = 0; k < 13; k++)
            acc = fmaf(xs[row * 13 + k], ws[col * 13 + k], acc);
        acc = fmaxf(acc, 0.0f);
        bf16 h = __float2bfloat16(acc);
        const size_t oi = (size_t)(row0 + row) * 512 + col;
        g_h1h[oi] = h;
        g_h1l[oi] = __float2bfloat16(acc - __bfloat162float(h));
    }
}

// ---------------- gather + pairwise interactions ---------------------------
// warp per sample; smem 28 rows x 32 float4, XOR-swizzled. Writes x hi/lo bf16.
#define ISMEM (4 * 28 * 32 * 16)
__global__ __launch_bounds__(128) void interact_kernel(
    const int* __restrict__ cat, const float* __restrict__ emb)
{
    extern __shared__ float4 fsm[];
    const int warp = threadIdx.x >> 5;
    const int lane = threadIdx.x & 31;
    const int b    = blockIdx.x * 4 + warp;
    float4* F = fsm + warp * (28 * 32);

    // gather indices first (all in flight), then rows (all in flight)
    int idxs[NCAT];
    #pragma unroll
    for (int t = 0; t < NCAT; t++) idxs[t] = cat[t * BATCH + b];

    float4 bv = ((const float4*)(g_bot + (size_t)b * EMB))[lane];
    F[lane] = bv;
    #pragma unroll
    for (int t = 0; t < NCAT; t++) {
        const int r = t + 1;
        F[r * 32 + (lane ^ ((r >> 2) & 7))] =
            ((const float4*)(emb + ((size_t)t * 100000 + idxs[t]) * EMB))[lane];
    }
    F[27 * 32 + (lane ^ 6)] = make_float4(0.f, 0.f, 0.f, 0.f);
    __syncwarp();

    bf16* xh = g_xh + (size_t)b * XDIM;
    bf16* xl = g_xl + (size_t)b * XDIM;

    // bottom -> x[0:128] (split), zero x[479:512]
    {
        uint32_t h0, l0, h1, l1;
        split2(bv.x, bv.y, h0, l0);
        split2(bv.z, bv.w, h1, l1);
        *(uint2*)(xh + lane * 4) = make_uint2(h0, h1);
        *(uint2*)(xl + lane * 4) = make_uint2(l0, l1);
    }
    const bf16 z = __float2bfloat16(0.0f);
    xh[480 + lane] = z; xl[480 + lane] = z;
    if (lane == 0) { xh[479] = z; xl[479] = z; }

    if (lane < 28) {
        int t = lane, R = 0;
        while (t >= R + 1) { t -= R + 1; R++; }
        const int C = t;
        const int sR = R & 7, sC = C & 7;

        float a[4][4];
        #pragma unroll
        for (int i = 0; i < 4; i++)
            #pragma unroll
            for (int j = 0; j < 4; j++) a[i][j] = 0.0f;

        #pragma unroll 4
        for (int d4 = 0; d4 < 32; d4++) {
            float4 fr[4], fc[4];
            #pragma unroll
            for (int i = 0; i < 4; i++)
                fr[i] = F[(4 * R + i) * 32 + (d4 ^ sR)];
            #pragma unroll
            for (int j = 0; j < 4; j++)
                fc[j] = F[(4 * C + j) * 32 + (d4 ^ sC)];
            #pragma unroll
            for (int i = 0; i < 4; i++)
                #pragma unroll
                for (int j = 0; j < 4; j++) {
                    a[i][j] = fmaf(fr[i].x, fc[j].x, a[i][j]);
                    a[i][j] = fmaf(fr[i].y, fc[j].y, a[i][j]);
                    a[i][j] = fmaf(fr[i].z, fc[j].z, a[i][j]);
                    a[i][j] = fmaf(fr[i].w, fc[j].w, a[i][j]);
                }
        }

        #pragma unroll
        for (int i = 0; i < 4; i++) {
            const int r = 4 * R + i;
            #pragma unroll
            for (int j = 0; j < 4; j++) {
                const int c = 4 * C + j;
                if (r < 27 && c < r) {
                    const float v = a[i][j];
                    const bf16 h = __float2bfloat16(v);
                    const int off = EMB + r * (r - 1) / 2 + c;
                    xh[off] = h;
                    xl[off] = __float2bfloat16(v - __bfloat162float(h));
                }
            }
        }
    }
}

// ---------------- weight prep: split fp32 -> bf16 hi/lo --------------------
__global__ __launch_bounds__(256) void split_w_kernel(
    const float* __restrict__ W, bf16* __restrict__ Wh, bf16* __restrict__ Wl,
    int n)
{
    const int i = blockIdx.x * 256 + threadIdx.x;
    if (i >= n) return;
    const float v = W[i];
    const bf16 h = __float2bfloat16(v);
    Wh[i] = h;
    Wl[i] = __float2bfloat16(v - __bfloat162float(h));
}

// tw1 [1024,480] -> padded [1024,512] hi/lo
__global__ __launch_bounds__(256) void pad_split_w1_kernel(const float* __restrict__ tw1)
{
    const int i = blockIdx.x * 256 + threadIdx.x;     // over 1024*512
    const int r = i >> 9, c = i & 511;
    const float v = (c < 480) ? tw1[r * 480 + c] : 0.0f;
    const bf16 h = __float2bfloat16(v);
    g_tw1h[i] = h;
    g_tw1l[i] = __float2bfloat16(v - __bfloat162float(h));
}

// ---------------- final layer: dot(256) + sigmoid ---------------------------
__global__ __launch_bounds__(256) void final_kernel(
    const float* __restrict__ w5, const float* __restrict__ b5,
    float* __restrict__ out)
{
    const int warp = threadIdx.x >> 5;
    const int lane = threadIdx.x & 31;
    const int b = blockIdx.x * 8 + warp;
    const float* row = g_t4 + (size_t)b * 256;
    float s = 0.0f;
    #pragma unroll
    for (int j = lane; j < 256; j += 32) s = fmaf(row[j], w5[j], s);
    #pragma unroll
    for (int o = 16; o; o >>= 1) s += __shfl_xor_sync(0xffffffffu, s, o);
    if (lane == 0) out[b] = 1.0f / (1.0f + expf(-(s + b5[0])));
}

// ---------------- launcher --------------------------------------------------
template <typename T>
static T* sym_addr(const void* symbol)
{
    void* p = nullptr;
    cudaGetSymbolAddress(&p, symbol);
    return (T*)p;
}

extern "C" void kernel_launch(void* const* d_in, const int* in_sizes, int n_in,
                              void* d_out, int out_size)
{
    const float* Xnum = (const float*)d_in[0];
    const int*   cat  = (const int*)  d_in[1];
    const float* emb  = (const float*)d_in[2];
    const float* bw1  = (const float*)d_in[3];
    const float* bb1  = (const float*)d_in[4];
    const float* bw2  = (const float*)d_in[5];
    const float* bb2  = (const float*)d_in[6];
    const float* bw3  = (const float*)d_in[7];
    const float* bb3  = (const float*)d_in[8];
    const float* tw1  = (const float*)d_in[9];
    const float* tb1  = (const float*)d_in[10];
    const float* tw2  = (const float*)d_in[11];
    const float* tb2  = (const float*)d_in[12];
    const float* tw3  = (const float*)d_in[13];
    const float* tb3  = (const float*)d_in[14];
    const float* tw4  = (const float*)d_in[15];
    const float* tb4  = (const float*)d_in[16];
    const float* tw5  = (const float*)d_in[17];
    const float* tb5  = (const float*)d_in[18];
    float* out = (float*)d_out;

    bf16* h1h = sym_addr<bf16>(g_h1h);   bf16* h1l = sym_addr<bf16>(g_h1l);
    bf16* h2h = sym_addr<bf16>(g_h2h);   bf16* h2l = sym_addr<bf16>(g_h2l);
    float* bot = sym_addr<float>(g_bot);
    bf16* xh  = sym_addr<bf16>(g_xh);    bf16* xl  = sym_addr<bf16>(g_xl);
    bf16* t1h = sym_addr<bf16>(g_t1h);   bf16* t1l = sym_addr<bf16>(g_t1l);
    bf16* t2h = sym_addr<bf16>(g_t2h);   bf16* t2l = sym_addr<bf16>(g_t2l);
    bf16* t3h = sym_addr<bf16>(g_t3h);   bf16* t3l = sym_addr<bf16>(g_t3l);
    float* t4 = sym_addr<float>(g_t4);
    bf16* w2h = sym_addr<bf16>(g_w2h);   bf16* w2l = sym_addr<bf16>(g_w2l);
    bf16* w3h = sym_addr<bf16>(g_w3h);   bf16* w3l = sym_addr<bf16>(g_w3l);
    bf16* u1h = sym_addr<bf16>(g_tw1h);  bf16* u1l = sym_addr<bf16>(g_tw1l);
    bf16* u2h = sym_addr<bf16>(g_tw2h);  bf16* u2l = sym_addr<bf16>(g_tw2l);
    bf16* u3h = sym_addr<bf16>(g_tw3h);  bf16* u3l = sym_addr<bf16>(g_tw3l);
    bf16* u4h = sym_addr<bf16>(g_tw4h);  bf16* u4l = sym_addr<bf16>(g_tw4l);

    cudaFuncSetAttribute(interact_kernel,
                         cudaFuncAttributeMaxDynamicSharedMemorySize, ISMEM);
    cudaFuncSetAttribute(gemm_tc,
                         cudaFuncAttributeMaxDynamicSharedMemorySize, GEMM_SMEM);

    // weight prep (~6 us total)
    split_w_kernel<<<(256 * 512 + 255) / 256, 256>>>(bw2, w2h, w2l, 256 * 512);
    split_w_kernel<<<(128 * 256 + 255) / 256, 256>>>(bw3, w3h, w3l, 128 * 256);
    pad_split_w1_kernel<<<(1024 * 512) / 256, 256>>>(tw1);
    split_w_kernel<<<(1024 * 1024 + 255) / 256, 256>>>(tw2, u2h, u2l, 1024 * 1024);
    split_w_kernel<<<(512 * 1024 + 255) / 256, 256>>>(tw3, u3h, u3l, 512 * 1024);
    split_w_kernel<<<(256 * 512 + 255) / 256, 256>>>(tw4, u4h, u4l, 256 * 512);

    // bottom MLP
    bottom1_kernel<<<BATCH / 32, 256>>>(Xnum, bw1, bb1);
    gemm_tc<<<dim3(2, BATCH / 128), 256, GEMM_SMEM>>>(
        h1h, h1l, w2h, w2l, bb2, nullptr, h2h, h2l, 512, 256, 1);
    gemm_tc<<<dim3(1, BATCH / 128), 256, GEMM_SMEM>>>(
        h2h, h2l, w3h, w3l, bb3, bot, nullptr, nullptr, 256, 128, 1);

    // gather + interactions -> x hi/lo [B, 512]
    interact_kernel<<<BATCH / 4, 128, ISMEM>>>(cat, emb);

    // top MLP
    gemm_tc<<<dim3(8, BATCH / 128), 256, GEMM_SMEM>>>(
        xh,  xl,  u1h, u1l, tb1, nullptr, t1h, t1l, 512, 1024, 1);
    gemm_tc<<<dim3(8, BATCH / 128), 256, GEMM_SMEM>>>(
        t1h, t1l, u2h, u2l, tb2, nullptr, t2h, t2l, 1024, 1024, 1);
    gemm_tc<<<dim3(4, BATCH / 128), 256, GEMM_SMEM>>>(
        t2h, t2l, u3h, u3l, tb3, nullptr, t3h, t3l, 1024, 512, 1);
    gemm_tc<<<dim3(2, BATCH / 128), 256, GEMM_SMEM>>>(
        t3h, t3l, u4h, u4l, tb4, t4, nullptr, nullptr, 512, 256, 1);

    // final dot + sigmoid
    final_kernel<<<BATCH / 8, 256>>>(tw5, tb5, out);
}

// round 6
// speedup vs baseline: 2.1919x; 2.1067x over previous
#include <cuda_runtime.h>
#include <cuda_fp16.h>
#include <cstdint>
#include <math.h>

#define BATCH   16384
#define EMB     128
#define NCAT    26
#define XDIM    512      /* 480 padded to 512 */

typedef __half fp16;

// ---------------- scratch (device globals; allocation-free) ----------------
__device__ fp16  g_h1 [BATCH * 512];
__device__ fp16  g_h2 [BATCH * 256];
__device__ fp16  g_bt [BATCH * 128];
__device__ fp16  g_x  [BATCH * XDIM];
__device__ fp16  g_t1 [BATCH * 1024];
__device__ fp16  g_t2 [BATCH * 1024];
__device__ fp16  g_t3 [BATCH * 512];
__device__ float g_t4 [BATCH * 256];
// converted weights
__device__ fp16  g_w2 [256 * 512];
__device__ fp16  g_w3 [128 * 256];
__device__ fp16  g_u1 [1024 * XDIM];    // tw1 padded 480 -> 512
__device__ fp16  g_u2 [1024 * 1024];
__device__ fp16  g_u3 [512 * 1024];
__device__ fp16  g_u4 [256 * 512];

// ======================= helpers ============================================
__device__ __forceinline__ uint32_t smem_u32(const void* p) {
    uint32_t a;
    asm("{ .reg .u64 t; cvta.to.shared.u64 t, %1; cvt.u32.u64 %0, t; }"
        : "=r"(a) : "l"(p));
    return a;
}

#define LDSM4(r0, r1, r2, r3, addr) \
    asm volatile("ldmatrix.sync.aligned.m8n8.x4.shared.b16 {%0,%1,%2,%3}, [%4];" \
        : "=r"(r0), "=r"(r1), "=r"(r2), "=r"(r3) : "r"(addr))

#define MMA_F16(c, a, b0, b1) \
    asm volatile("mma.sync.aligned.m16n8k16.row.col.f32.f16.f16.f32 " \
        "{%0,%1,%2,%3}, {%4,%5,%6,%7}, {%8,%9}, {%0,%1,%2,%3};" \
        : "+f"((c)[0]), "+f"((c)[1]), "+f"((c)[2]), "+f"((c)[3]) \
        : "r"((a)[0]), "r"((a)[1]), "r"((a)[2]), "r"((a)[3]), "r"(b0), "r"(b1))

#define CP16(dst, src) \
    asm volatile("cp.async.cg.shared.global [%0], [%1], 16;" :: "r"(dst), "l"(src))
#define CP_COMMIT() asm volatile("cp.async.commit_group;" ::: "memory")
#define CP_WAIT2()  asm volatile("cp.async.wait_group 2;" ::: "memory")

// ============ tensor-core GEMM ==============================================
// C = relu?(A @ W^T + b). A [M,K], W [N,K] fp16. Out: Cf fp32 or Ch fp16.
// 128x128 CTA tile, 8 warps (2x4 of 64x32), K-chunk 32, 4-stage cp.async.
// smem per stage (16KB): A 8KB + W 8KB, each as 8x8-fp16-matrix-contiguous
// (128B mats, mat idx = (row>>3)*4 + koct). bias at 65536. Total 66048.
#define GEMM_SMEM (4 * 16384 + 512)

__global__ __launch_bounds__(256, 2) void gemm_tc(
    const fp16* __restrict__ A, const fp16* __restrict__ W,
    const float* __restrict__ bias,
    float* __restrict__ Cf, fp16* __restrict__ Ch,
    int K, int N, int relu)
{
    extern __shared__ unsigned char smem[];
    const uint32_t sb = smem_u32(smem);
    const int tid    = threadIdx.x;
    const int lane   = tid & 31;
    const int w      = tid >> 5;
    const int warp_m = w >> 2;
    const int warp_n = w & 3;
    const int row0   = blockIdx.y * 128;
    const int col0   = blockIdx.x * 128;

    float* sbias = (float*)(smem + 65536);
    if (tid < 128) sbias[tid] = bias[col0 + tid];

    const fp16* Ab = A + (size_t)row0 * K;
    const fp16* Wb = W + (size_t)col0 * K;

    // cp.async mapping: thread -> (row, 2 segs of 8 fp16)
    const int crow  = tid >> 1;
    const int cseg0 = (tid & 1) * 2;
    const uint32_t soffA = (uint32_t)(((crow >> 3) * 4) * 128 + (crow & 7) * 16);

    const int nk = K >> 5;

    // prologue: issue stages 0..2
    #pragma unroll
    for (int pc = 0; pc < 3; pc++) {
        if (pc < nk) {
            const uint32_t bufb = sb + (uint32_t)pc * 16384;
            #pragma unroll
            for (int s = 0; s < 2; s++) {
                const int seg = cseg0 + s;
                const uint32_t so = bufb + soffA + (uint32_t)seg * 128;
                const size_t  go = (size_t)crow * K + pc * 32 + seg * 8;
                CP16(so,        Ab + go);
                CP16(so + 8192, Wb + go);
            }
        }
        CP_COMMIT();
    }

    // ldmatrix lane offsets
    const int g  = lane >> 3;
    const int lr = lane & 7;
    const uint32_t laneA = (uint32_t)((g & 1) * 512 + (g >> 1) * 128 + lr * 16);
    const uint32_t laneB = (uint32_t)((g & 1) * 128 + (g >> 1) * 512 + lr * 16);

    float acc[4][4][4];
    #pragma unroll
    for (int i = 0; i < 4; i++)
        #pragma unroll
        for (int j = 0; j < 4; j++)
            #pragma unroll
            for (int e = 0; e < 4; e++) acc[i][j][e] = 0.0f;

    for (int ck = 0; ck < nk; ck++) {
        CP_WAIT2();            // stage ck complete (2 newer may be in flight)
        __syncthreads();       // all warps done consuming stage ck-1
        const uint32_t bufb = sb + (uint32_t)(ck & 3) * 16384;

        #pragma unroll
        for (int kk = 0; kk < 2; kk++) {
            const uint32_t koff = (uint32_t)(kk * 256);
            uint32_t ah[4][4], bh[4][2];
            #pragma unroll
            for (int mt = 0; mt < 4; mt++) {
                const uint32_t ta = bufb
                    + (uint32_t)((warp_m * 8 + mt * 2) * 512) + koff + laneA;
                LDSM4(ah[mt][0], ah[mt][1], ah[mt][2], ah[mt][3], ta);
            }
            #pragma unroll
            for (int np = 0; np < 2; np++) {
                const uint32_t tb = bufb + 8192
                    + (uint32_t)((warp_n * 4 + np * 2) * 512) + koff + laneB;
                uint32_t r0, r1, r2, r3;
                LDSM4(r0, r1, r2, r3, tb);
                bh[np*2][0] = r0; bh[np*2][1] = r1;
                bh[np*2+1][0] = r2; bh[np*2+1][1] = r3;
            }
            #pragma unroll
            for (int mt = 0; mt < 4; mt++)
                #pragma unroll
                for (int nt = 0; nt < 4; nt++)
                    MMA_F16(acc[mt][nt], ah[mt], bh[nt][0], bh[nt][1]);
        }

        // issue stage ck+3 into buffer (ck+3)&3 (consumed at iteration ck-1)
        if (ck + 3 < nk) {
            const uint32_t bufb2 = sb + (uint32_t)((ck + 3) & 3) * 16384;
            #pragma unroll
            for (int s = 0; s < 2; s++) {
                const int seg = cseg0 + s;
                const uint32_t so = bufb2 + soffA + (uint32_t)seg * 128;
                const size_t  go = (size_t)crow * K + (ck + 3) * 32 + seg * 8;
                CP16(so,        Ab + go);
                CP16(so + 8192, Wb + go);
            }
        }
        CP_COMMIT();   // unconditional: keeps group accounting exact
    }

    // ---- epilogue: bias + relu, fp32 or fp16 stores ----
    const int q  = lane >> 2;
    const int tq = lane & 3;
    #pragma unroll
    for (int mt = 0; mt < 4; mt++) {
        const int r0g = row0 + warp_m * 64 + mt * 16 + q;
        #pragma unroll
        for (int nt = 0; nt < 4; nt++) {
            const int cl = warp_n * 32 + nt * 8 + tq * 2;
            const float bx = sbias[cl], by = sbias[cl + 1];
            float v0 = acc[mt][nt][0] + bx, v1 = acc[mt][nt][1] + by;
            float v2 = acc[mt][nt][2] + bx, v3 = acc[mt][nt][3] + by;
            if (relu) {
                v0 = fmaxf(v0, 0.0f); v1 = fmaxf(v1, 0.0f);
                v2 = fmaxf(v2, 0.0f); v3 = fmaxf(v3, 0.0f);
            }
            const size_t o0 = (size_t)r0g * N + col0 + cl;
            const size_t o1 = (size_t)(r0g + 8) * N + col0 + cl;
            if (Cf) {
                *(float2*)(Cf + o0) = make_float2(v0, v1);
                *(float2*)(Cf + o1) = make_float2(v2, v3);
            }
            if (Ch) {
                *(__half2*)(Ch + o0) = __floats2half2_rn(v0, v1);
                *(__half2*)(Ch + o1) = __floats2half2_rn(v2, v3);
            }
        }
    }
}

// ---------------- bottom layer 1: [B,13] -> [B,512] fp16, relu -------------
__global__ __launch_bounds__(256) void bottom1_kernel(
    const float* __restrict__ X, const float* __restrict__ W,
    const float* __restrict__ bias)
{
    __shared__ float ws[512 * 13];
    __shared__ float bs[512];
    __shared__ float xs[32 * 13];
    const int tid  = threadIdx.x;
    const int row0 = blockIdx.x * 32;

    for (int i = tid; i < 512 * 13; i += 256) ws[i] = W[i];
    for (int i = tid; i < 512;      i += 256) bs[i] = bias[i];
    for (int i = tid; i < 32 * 13;  i += 256) xs[i] = X[row0 * 13 + i];
    __syncthreads();

    for (int o = tid; o < 32 * 512; o += 256) {
        const int col = o & 511;
        const int row = o >> 9;
        float acc = bs[col];
        #pragma unroll
        for (int k = 0; k < 13; k++)
            acc = fmaf(xs[row * 13 + k], ws[col * 13 + k], acc);
        g_h1[(size_t)(row0 + row) * 512 + col] = __float2half(fmaxf(acc, 0.0f));
    }
}

// ---------------- gather + pairwise interactions ---------------------------
// warp per sample, 4/block. smem: 28 rows x 32 uint2 (4 fp16 each), XOR-
// swizzled by tile row: element(r, d4) at r*32 + (d4 ^ (r>>2)).
__global__ __launch_bounds__(128) void interact_kernel(
    const int* __restrict__ cat, const float* __restrict__ emb)
{
    __shared__ uint2 fsm[4 * 28 * 32];
    const int warp = threadIdx.x >> 5;
    const int lane = threadIdx.x & 31;
    const int b    = blockIdx.x * 4 + warp;
    uint2* F = fsm + warp * (28 * 32);

    int idxs[NCAT];
    #pragma unroll
    for (int t = 0; t < NCAT; t++) idxs[t] = cat[t * BATCH + b];

    // row 0: bottom (already fp16)
    uint2 bv = ((const uint2*)(g_bt + (size_t)b * EMB))[lane];
    F[lane] = bv;
    // rows 1..26: embeddings fp32 -> fp16
    #pragma unroll
    for (int t = 0; t < NCAT; t++) {
        const int r = t + 1;
        float4 e = ((const float4*)(emb + ((size_t)t * 100000 + idxs[t]) * EMB))[lane];
        uint2 p;
        *(__half2*)&p.x = __floats2half2_rn(e.x, e.y);
        *(__half2*)&p.y = __floats2half2_rn(e.z, e.w);
        F[r * 32 + (lane ^ (r >> 2))] = p;
    }
    F[27 * 32 + (lane ^ 6)] = make_uint2(0u, 0u);
    __syncwarp();

    fp16* xrow = g_x + (size_t)b * XDIM;

    // bottom -> x[0:128]; zero x[479:512]
    ((uint2*)xrow)[lane] = bv;
    ((uint2*)(xrow + 480))[lane & 7] = make_uint2(0u, 0u);
    if (lane == 0) xrow[479] = __float2half(0.0f);

    if (lane < 28) {
        int t = lane, R = 0;
        while (t >= R + 1) { t -= R + 1; R++; }
        const int C = t;

        float a[4][4];
        #pragma unroll
        for (int i = 0; i < 4; i++)
            #pragma unroll
            for (int j = 0; j < 4; j++) a[i][j] = 0.0f;

        #pragma unroll 4
        for (int d4 = 0; d4 < 32; d4++) {
            float4 fr[4], fc[4];
            #pragma unroll
            for (int i = 0; i < 4; i++) {
                uint2 u = F[(4 * R + i) * 32 + (d4 ^ R)];
                float2 p0 = __half22float2(*(__half2*)&u.x);
                float2 p1 = __half22float2(*(__half2*)&u.y);
                fr[i] = make_float4(p0.x, p0.y, p1.x, p1.y);
            }
            #pragma unroll
            for (int j = 0; j < 4; j++) {
                uint2 u = F[(4 * C + j) * 32 + (d4 ^ C)];
                float2 p0 = __half22float2(*(__half2*)&u.x);
                float2 p1 = __half22float2(*(__half2*)&u.y);
                fc[j] = make_float4(p0.x, p0.y, p1.x, p1.y);
            }
            #pragma unroll
            for (int i = 0; i < 4; i++)
                #pragma unroll
                for (int j = 0; j < 4; j++) {
                    a[i][j] = fmaf(fr[i].x, fc[j].x, a[i][j]);
                    a[i][j] = fmaf(fr[i].y, fc[j].y, a[i][j]);
                    a[i][j] = fmaf(fr[i].z, fc[j].z, a[i][j]);
                    a[i][j] = fmaf(fr[i].w, fc[j].w, a[i][j]);
                }
        }

        #pragma unroll
        for (int i = 0; i < 4; i++) {
            const int r = 4 * R + i;
            #pragma unroll
            for (int j = 0; j < 4; j++) {
                const int c = 4 * C + j;
                if (r < 27 && c < r)
                    xrow[EMB + r * (r - 1) / 2 + c] = __float2half(a[i][j]);
            }
        }
    }
}

// ---------------- weight prep: fp32 -> fp16 --------------------------------
__global__ __launch_bounds__(256) void conv_w_kernel(
    const float* __restrict__ W, fp16* __restrict__ Wh, int n)
{
    const int i = blockIdx.x * 256 + threadIdx.x;
    if (i < n) Wh[i] = __float2half(W[i]);
}

// tw1 [1024,480] -> padded [1024,512] fp16
__global__ __launch_bounds__(256) void pad_w1_kernel(const float* __restrict__ tw1)
{
    const int i = blockIdx.x * 256 + threadIdx.x;     // over 1024*512
    const int r = i >> 9, c = i & 511;
    g_u1[i] = __float2half((c < 480) ? tw1[r * 480 + c] : 0.0f);
}

// ---------------- final layer: dot(256) + sigmoid ---------------------------
__global__ __launch_bounds__(256) void final_kernel(
    const float* __restrict__ w5, const float* __restrict__ b5,
    float* __restrict__ out)
{
    const int warp = threadIdx.x >> 5;
    const int lane = threadIdx.x & 31;
    const int b = blockIdx.x * 8 + warp;
    const float* row = g_t4 + (size_t)b * 256;
    float s = 0.0f;
    #pragma unroll
    for (int j = lane; j < 256; j += 32) s = fmaf(row[j], w5[j], s);
    #pragma unroll
    for (int o = 16; o; o >>= 1) s += __shfl_xor_sync(0xffffffffu, s, o);
    if (lane == 0) out[b] = 1.0f / (1.0f + expf(-(s + b5[0])));
}

// ---------------- launcher --------------------------------------------------
template <typename T>
static T* sym_addr(const void* symbol)
{
    void* p = nullptr;
    cudaGetSymbolAddress(&p, symbol);
    return (T*)p;
}

extern "C" void kernel_launch(void* const* d_in, const int* in_sizes, int n_in,
                              void* d_out, int out_size)
{
    const float* Xnum = (const float*)d_in[0];
    const int*   cat  = (const int*)  d_in[1];
    const float* emb  = (const float*)d_in[2];
    const float* bw1  = (const float*)d_in[3];
    const float* bb1  = (const float*)d_in[4];
    const float* bw2  = (const float*)d_in[5];
    const float* bb2  = (const float*)d_in[6];
    const float* bw3  = (const float*)d_in[7];
    const float* bb3  = (const float*)d_in[8];
    const float* tw1  = (const float*)d_in[9];
    const float* tb1  = (const float*)d_in[10];
    const float* tw2  = (const float*)d_in[11];
    const float* tb2  = (const float*)d_in[12];
    const float* tw3  = (const float*)d_in[13];
    const float* tb3  = (const float*)d_in[14];
    const float* tw4  = (const float*)d_in[15];
    const float* tb4  = (const float*)d_in[16];
    const float* tw5  = (const float*)d_in[17];
    const float* tb5  = (const float*)d_in[18];
    float* out = (float*)d_out;

    fp16* h1 = sym_addr<fp16>(g_h1);
    fp16* h2 = sym_addr<fp16>(g_h2);
    fp16* bt = sym_addr<fp16>(g_bt);
    fp16* x  = sym_addr<fp16>(g_x);
    fp16* t1 = sym_addr<fp16>(g_t1);
    fp16* t2 = sym_addr<fp16>(g_t2);
    fp16* t3 = sym_addr<fp16>(g_t3);
    float* t4 = sym_addr<float>(g_t4);
    fp16* w2 = sym_addr<fp16>(g_w2);
    fp16* w3 = sym_addr<fp16>(g_w3);
    fp16* u1 = sym_addr<fp16>(g_u1);
    fp16* u2 = sym_addr<fp16>(g_u2);
    fp16* u3 = sym_addr<fp16>(g_u3);
    fp16* u4 = sym_addr<fp16>(g_u4);

    cudaFuncSetAttribute(gemm_tc,
                         cudaFuncAttributeMaxDynamicSharedMemorySize, GEMM_SMEM);

    // weight prep (~5 us total)
    conv_w_kernel<<<(256 * 512 + 255) / 256, 256>>>(bw2, w2, 256 * 512);
    conv_w_kernel<<<(128 * 256 + 255) / 256, 256>>>(bw3, w3, 128 * 256);
    pad_w1_kernel<<<(1024 * 512) / 256, 256>>>(tw1);
    conv_w_kernel<<<(1024 * 1024 + 255) / 256, 256>>>(tw2, u2, 1024 * 1024);
    conv_w_kernel<<<(512 * 1024 + 255) / 256, 256>>>(tw3, u3, 512 * 1024);
    conv_w_kernel<<<(256 * 512 + 255) / 256, 256>>>(tw4, u4, 256 * 512);

    // bottom MLP
    bottom1_kernel<<<BATCH / 32, 256>>>(Xnum, bw1, bb1);
    gemm_tc<<<dim3(2, BATCH / 128), 256, GEMM_SMEM>>>(
        h1, w2, bb2, nullptr, h2, 512, 256, 1);
    gemm_tc<<<dim3(1, BATCH / 128), 256, GEMM_SMEM>>>(
        h2, w3, bb3, nullptr, bt, 256, 128, 1);

    // gather + interactions -> x [B, 512] fp16
    interact_kernel<<<BATCH / 4, 128>>>(cat, emb);

    // top MLP
    gemm_tc<<<dim3(8, BATCH / 128), 256, GEMM_SMEM>>>(
        x,  u1, tb1, nullptr, t1, 512, 1024, 1);
    gemm_tc<<<dim3(8, BATCH / 128), 256, GEMM_SMEM>>>(
        t1, u2, tb2, nullptr, t2, 1024, 1024, 1);
    gemm_tc<<<dim3(4, BATCH / 128), 256, GEMM_SMEM>>>(
        t2, u3, tb3, nullptr, t3, 1024, 512, 1);
    gemm_tc<<<dim3(2, BATCH / 128), 256, GEMM_SMEM>>>(
        t3, u4, tb4, t4, nullptr, 512, 256, 1);

    // final dot + sigmoid
    final_kernel<<<BATCH / 8, 256>>>(tw5, tb5, out);
}

// round 7
// speedup vs baseline: 2.3539x; 1.0739x over previous
#include <cuda_runtime.h>
#include <cuda_fp16.h>
#include <cstdint>
#include <math.h>

#define BATCH   16384
#define EMB     128
#define NCAT    26
#define XDIM    480

typedef __half fp16;

// ---------------- scratch (device globals; allocation-free) ----------------
__device__ fp16  g_h1 [BATCH * 512];
__device__ fp16  g_h2 [BATCH * 256];
__device__ fp16  g_bt [BATCH * 128];
__device__ fp16  g_x  [BATCH * XDIM];
__device__ fp16  g_t1 [BATCH * 1024];
__device__ fp16  g_t2 [BATCH * 1024];
__device__ fp16  g_t3 [BATCH * 512];
__device__ float g_t4 [BATCH * 256];
// converted weights
__device__ fp16  g_w2 [256 * 512];
__device__ fp16  g_w3 [128 * 256];
__device__ fp16  g_u1 [1024 * XDIM];
__device__ fp16  g_u2 [1024 * 1024];
__device__ fp16  g_u3 [512 * 1024];
__device__ fp16  g_u4 [256 * 512];

// ======================= helpers ============================================
__device__ __forceinline__ uint32_t smem_u32(const void* p) {
    uint32_t a;
    asm("{ .reg .u64 t; cvta.to.shared.u64 t, %1; cvt.u32.u64 %0, t; }"
        : "=r"(a) : "l"(p));
    return a;
}

#define LDSM4(r0, r1, r2, r3, addr) \
    asm volatile("ldmatrix.sync.aligned.m8n8.x4.shared.b16 {%0,%1,%2,%3}, [%4];" \
        : "=r"(r0), "=r"(r1), "=r"(r2), "=r"(r3) : "r"(addr))

#define MMA_F16(c, a, b0, b1) \
    asm volatile("mma.sync.aligned.m16n8k16.row.col.f32.f16.f16.f32 " \
        "{%0,%1,%2,%3}, {%4,%5,%6,%7}, {%8,%9}, {%0,%1,%2,%3};" \
        : "+f"((c)[0]), "+f"((c)[1]), "+f"((c)[2]), "+f"((c)[3]) \
        : "r"((a)[0]), "r"((a)[1]), "r"((a)[2]), "r"((a)[3]), "r"(b0), "r"(b1))

#define CP16(dst, src) \
    asm volatile("cp.async.cg.shared.global [%0], [%1], 16;" :: "r"(dst), "l"(src))
#define CP_COMMIT() asm volatile("cp.async.commit_group;" ::: "memory")
#define CP_WAIT2()  asm volatile("cp.async.wait_group 2;" ::: "memory")

// ============ tensor-core GEMM ==============================================
// C = relu?(A @ W^T + b). A [M,K], W [N,K] fp16. Out: Cf fp32 or Ch fp16.
// 128x128 CTA tile, 8 warps (2x4 of 64x32), K-chunk 32, 4-stage cp.async.
// smem per stage (16KB): A 8KB + W 8KB, each as 8x8-fp16-matrix-contiguous
// (128B mats, mat idx = (row>>3)*4 + koct). bias at 65536. Total 66048.
// K must be a multiple of 32 with rows 16B-aligned (K % 8 == 0 suffices).
#define GEMM_SMEM (4 * 16384 + 512)

__global__ __launch_bounds__(256, 2) void gemm_tc(
    const fp16* __restrict__ A, const fp16* __restrict__ W,
    const float* __restrict__ bias,
    float* __restrict__ Cf, fp16* __restrict__ Ch,
    int K, int N, int relu)
{
    extern __shared__ unsigned char smem[];
    const uint32_t sb = smem_u32(smem);
    const int tid    = threadIdx.x;
    const int lane   = tid & 31;
    const int w      = tid >> 5;
    const int warp_m = w >> 2;
    const int warp_n = w & 3;
    const int row0   = blockIdx.y * 128;
    const int col0   = blockIdx.x * 128;

    float* sbias = (float*)(smem + 65536);
    if (tid < 128) sbias[tid] = bias[col0 + tid];

    const fp16* Ab = A + (size_t)row0 * K;
    const fp16* Wb = W + (size_t)col0 * K;

    // cp.async mapping: thread -> (row, 2 segs of 8 fp16)
    const int crow  = tid >> 1;
    const int cseg0 = (tid & 1) * 2;
    const uint32_t soffA = (uint32_t)(((crow >> 3) * 4) * 128 + (crow & 7) * 16);

    const int nk = K >> 5;

    // prologue: issue stages 0..2
    #pragma unroll
    for (int pc = 0; pc < 3; pc++) {
        if (pc < nk) {
            const uint32_t bufb = sb + (uint32_t)pc * 16384;
            #pragma unroll
            for (int s = 0; s < 2; s++) {
                const int seg = cseg0 + s;
                const uint32_t so = bufb + soffA + (uint32_t)seg * 128;
                const size_t  go = (size_t)crow * K + pc * 32 + seg * 8;
                CP16(so,        Ab + go);
                CP16(so + 8192, Wb + go);
            }
        }
        CP_COMMIT();
    }

    // ldmatrix lane offsets
    const int g  = lane >> 3;
    const int lr = lane & 7;
    const uint32_t laneA = (uint32_t)((g & 1) * 512 + (g >> 1) * 128 + lr * 16);
    const uint32_t laneB = (uint32_t)((g & 1) * 128 + (g >> 1) * 512 + lr * 16);

    float acc[4][4][4];
    #pragma unroll
    for (int i = 0; i < 4; i++)
        #pragma unroll
        for (int j = 0; j < 4; j++)
            #pragma unroll
            for (int e = 0; e < 4; e++) acc[i][j][e] = 0.0f;

    for (int ck = 0; ck < nk; ck++) {
        CP_WAIT2();            // stage ck complete (2 newer may be in flight)
        __syncthreads();       // all warps done consuming stage ck-1
        const uint32_t bufb = sb + (uint32_t)(ck & 3) * 16384;

        #pragma unroll
        for (int kk = 0; kk < 2; kk++) {
            const uint32_t koff = (uint32_t)(kk * 256);
            uint32_t ah[4][4], bh[4][2];
            #pragma unroll
            for (int mt = 0; mt < 4; mt++) {
                const uint32_t ta = bufb
                    + (uint32_t)((warp_m * 8 + mt * 2) * 512) + koff + laneA;
                LDSM4(ah[mt][0], ah[mt][1], ah[mt][2], ah[mt][3], ta);
            }
            #pragma unroll
            for (int np = 0; np < 2; np++) {
                const uint32_t tb = bufb + 8192
                    + (uint32_t)((warp_n * 4 + np * 2) * 512) + koff + laneB;
                uint32_t r0, r1, r2, r3;
                LDSM4(r0, r1, r2, r3, tb);
                bh[np*2][0] = r0; bh[np*2][1] = r1;
                bh[np*2+1][0] = r2; bh[np*2+1][1] = r3;
            }
            #pragma unroll
            for (int mt = 0; mt < 4; mt++)
                #pragma unroll
                for (int nt = 0; nt < 4; nt++)
                    MMA_F16(acc[mt][nt], ah[mt], bh[nt][0], bh[nt][1]);
        }

        // issue stage ck+3 into buffer (ck+3)&3 (consumed at iteration ck-1)
        if (ck + 3 < nk) {
            const uint32_t bufb2 = sb + (uint32_t)((ck + 3) & 3) * 16384;
            #pragma unroll
            for (int s = 0; s < 2; s++) {
                const int seg = cseg0 + s;
                const uint32_t so = bufb2 + soffA + (uint32_t)seg * 128;
                const size_t  go = (size_t)crow * K + (ck + 3) * 32 + seg * 8;
                CP16(so,        Ab + go);
                CP16(so + 8192, Wb + go);
            }
        }
        CP_COMMIT();   // unconditional: keeps group accounting exact
    }

    // ---- epilogue: bias + relu, fp32 or fp16 stores ----
    const int q  = lane >> 2;
    const int tq = lane & 3;
    #pragma unroll
    for (int mt = 0; mt < 4; mt++) {
        const int r0g = row0 + warp_m * 64 + mt * 16 + q;
        #pragma unroll
        for (int nt = 0; nt < 4; nt++) {
            const int cl = warp_n * 32 + nt * 8 + tq * 2;
            const float bx = sbias[cl], by = sbias[cl + 1];
            float v0 = acc[mt][nt][0] + bx, v1 = acc[mt][nt][1] + by;
            float v2 = acc[mt][nt][2] + bx, v3 = acc[mt][nt][3] + by;
            if (relu) {
                v0 = fmaxf(v0, 0.0f); v1 = fmaxf(v1, 0.0f);
                v2 = fmaxf(v2, 0.0f); v3 = fmaxf(v3, 0.0f);
            }
            const size_t o0 = (size_t)r0g * N + col0 + cl;
            const size_t o1 = (size_t)(r0g + 8) * N + col0 + cl;
            if (Cf) {
                *(float2*)(Cf + o0) = make_float2(v0, v1);
                *(float2*)(Cf + o1) = make_float2(v2, v3);
            }
            if (Ch) {
                *(__half2*)(Ch + o0) = __floats2half2_rn(v0, v1);
                *(__half2*)(Ch + o1) = __floats2half2_rn(v2, v3);
            }
        }
    }
}

// ---------------- bottom layer 1: [B,13] -> [B,512] fp16, relu -------------
__global__ __launch_bounds__(256) void bottom1_kernel(
    const float* __restrict__ X, const float* __restrict__ W,
    const float* __restrict__ bias)
{
    __shared__ float ws[512 * 13];
    __shared__ float bs[512];
    __shared__ float xs[32 * 13];
    const int tid  = threadIdx.x;
    const int row0 = blockIdx.x * 32;

    for (int i = tid; i < 512 * 13; i += 256) ws[i] = W[i];
    for (int i = tid; i < 512;      i += 256) bs[i] = bias[i];
    for (int i = tid; i < 32 * 13;  i += 256) xs[i] = X[row0 * 13 + i];
    __syncthreads();

    for (int o = tid; o < 32 * 512; o += 256) {
        const int col = o & 511;
        const int row = o >> 9;
        float acc = bs[col];
        #pragma unroll
        for (int k = 0; k < 13; k++)
            acc = fmaf(xs[row * 13 + k], ws[col * 13 + k], acc);
        g_h1[(size_t)(row0 + row) * 512 + col] = __float2half(fmaxf(acc, 0.0f));
    }
}

// ---------------- gather + pairwise interactions (HMMA Gram) ---------------
// warp per sample, 4/block. Per sample: feats padded to 32 rows x 128 cols
// fp16 in smem, 8x8-matrix-contiguous (128B mats, mat = (r>>3)*16 + (c>>3)),
// inner offset XOR-swizzled by (mat&7)<<4 for conflict-free stores AND lds.
// Gram D[32,32] = F @ F^T via 64 m16n8k16 MMAs; tril written to g_x.
__global__ __launch_bounds__(128) void interact_kernel(
    const int* __restrict__ cat, const float* __restrict__ emb)
{
    __shared__ __align__(16) unsigned char ism[4 * 8192];
    const int warp = threadIdx.x >> 5;
    const int lane = threadIdx.x & 31;
    const int b    = blockIdx.x * 4 + warp;
    unsigned char* F = ism + warp * 8192;
    const uint32_t fb = smem_u32(F);

    int idxs[NCAT];
    #pragma unroll
    for (int t = 0; t < NCAT; t++) idxs[t] = cat[t * BATCH + b];

    // store 4 fp16 (8B) at (row r, cols lane*4 .. lane*4+3)
    const int c0   = lane * 4;
    const int matc = c0 >> 3;
    const int innc = (c0 & 7) * 2;

    // row 0: bottom (already fp16)
    uint2 bv = ((const uint2*)(g_bt + (size_t)b * EMB))[lane];
    {
        const int mat = matc;                       // r=0
        *(uint2*)(F + mat * 128 + (innc ^ ((mat & 7) << 4))) = bv;
    }
    // rows 1..26: embeddings fp32 -> fp16
    #pragma unroll
    for (int t = 0; t < NCAT; t++) {
        const int r = t + 1;
        float4 e = ((const float4*)(emb + ((size_t)t * 100000 + idxs[t]) * EMB))[lane];
        uint2 p;
        *(__half2*)&p.x = __floats2half2_rn(e.x, e.y);
        *(__half2*)&p.y = __floats2half2_rn(e.z, e.w);
        const int mat = ((r >> 3) << 4) + matc;
        *(uint2*)(F + mat * 128 + ((((r & 7) << 4) + innc) ^ ((mat & 7) << 4))) = p;
    }
    // rows 27..31: zeros
    #pragma unroll
    for (int r = 27; r < 32; r++) {
        const int mat = ((r >> 3) << 4) + matc;
        *(uint2*)(F + mat * 128 + ((((r & 7) << 4) + innc) ^ ((mat & 7) << 4))) =
            make_uint2(0u, 0u);
    }
    __syncwarp();

    fp16* xrow = g_x + (size_t)b * XDIM;
    ((uint2*)xrow)[lane] = bv;            // x[0:128] = bottom
    if (lane == 0) xrow[479] = __float2half(0.0f);   // pad column

    // ---- Gram via HMMA: D = F(32x128) @ F(32x128)^T ----
    const int g2 = lane >> 3;
    const int lr = lane & 7;

    float acc[2][4][4];
    #pragma unroll
    for (int i = 0; i < 2; i++)
        #pragma unroll
        for (int j = 0; j < 4; j++)
            #pragma unroll
            for (int e = 0; e < 4; e++) acc[i][j][e] = 0.0f;

    #pragma unroll
    for (int k = 0; k < 8; k++) {         // k16 steps over K=128
        uint32_t a[2][4], bb[4][2];
        #pragma unroll
        for (int mt = 0; mt < 2; mt++) {
            const int mA = ((mt * 2 + (g2 & 1)) << 4) + (k * 2 + (g2 >> 1));
            const uint32_t ad = fb + (uint32_t)(mA * 128)
                              + (uint32_t)((lr * 16) ^ ((mA & 7) << 4));
            LDSM4(a[mt][0], a[mt][1], a[mt][2], a[mt][3], ad);
        }
        #pragma unroll
        for (int np = 0; np < 2; np++) {   // n16 halves
            const int mB = ((np * 2 + (g2 >> 1)) << 4) + (k * 2 + (g2 & 1));
            const uint32_t bd = fb + (uint32_t)(mB * 128)
                              + (uint32_t)((lr * 16) ^ ((mB & 7) << 4));
            uint32_t r0, r1, r2, r3;
            LDSM4(r0, r1, r2, r3, bd);
            bb[np*2][0] = r0;   bb[np*2][1] = r1;
            bb[np*2+1][0] = r2; bb[np*2+1][1] = r3;
        }
        #pragma unroll
        for (int mt = 0; mt < 2; mt++)
            #pragma unroll
            for (int nt = 0; nt < 4; nt++)
                MMA_F16(acc[mt][nt], a[mt], bb[nt][0], bb[nt][1]);
    }

    // ---- write lower triangle (c < r < 27) -> x[128 + r(r-1)/2 + c] ----
    const int q  = lane >> 2;
    const int tq = lane & 3;
    #pragma unroll
    for (int mt = 0; mt < 2; mt++) {
        #pragma unroll
        for (int nt = 0; nt < 4; nt++) {
            const int r1 = mt * 16 + q;
            const int r2 = r1 + 8;
            const int cA = nt * 8 + tq * 2;
            const int cB = cA + 1;
            if (r1 < 27) {
                if (cA < r1) xrow[EMB + r1 * (r1 - 1) / 2 + cA] = __float2half(acc[mt][nt][0]);
                if (cB < r1) xrow[EMB + r1 * (r1 - 1) / 2 + cB] = __float2half(acc[mt][nt][1]);
            }
            if (r2 < 27) {
                if (cA < r2) xrow[EMB + r2 * (r2 - 1) / 2 + cA] = __float2half(acc[mt][nt][2]);
                if (cB < r2) xrow[EMB + r2 * (r2 - 1) / 2 + cB] = __float2half(acc[mt][nt][3]);
            }
        }
    }
}

// ---------------- merged weight prep: fp32 -> fp16, all layers -------------
#define N_W2 (256 * 512)
#define N_W3 (128 * 256)
#define N_U1 (1024 * XDIM)
#define N_U2 (1024 * 1024)
#define N_U3 (512 * 1024)
#define N_U4 (256 * 512)
#define N_PREP (N_W2 + N_W3 + N_U1 + N_U2 + N_U3 + N_U4)

__global__ __launch_bounds__(256) void prep_kernel(
    const float* __restrict__ bw2, const float* __restrict__ bw3,
    const float* __restrict__ tw1, const float* __restrict__ tw2,
    const float* __restrict__ tw3, const float* __restrict__ tw4)
{
    int i = blockIdx.x * 256 + threadIdx.x;
    if (i >= N_PREP) return;
    if (i < N_W2) { g_w2[i] = __float2half(bw2[i]); return; }
    i -= N_W2;
    if (i < N_W3) { g_w3[i] = __float2half(bw3[i]); return; }
    i -= N_W3;
    if (i < N_U1) { g_u1[i] = __float2half(tw1[i]); return; }
    i -= N_U1;
    if (i < N_U2) { g_u2[i] = __float2half(tw2[i]); return; }
    i -= N_U2;
    if (i < N_U3) { g_u3[i] = __float2half(tw3[i]); return; }
    i -= N_U3;
    g_u4[i] = __float2half(tw4[i]);
}

// ---------------- final layer: dot(256) + sigmoid ---------------------------
__global__ __launch_bounds__(256) void final_kernel(
    const float* __restrict__ w5, const float* __restrict__ b5,
    float* __restrict__ out)
{
    const int warp = threadIdx.x >> 5;
    const int lane = threadIdx.x & 31;
    const int b = blockIdx.x * 8 + warp;
    const float* row = g_t4 + (size_t)b * 256;
    float s = 0.0f;
    #pragma unroll
    for (int j = lane; j < 256; j += 32) s = fmaf(row[j], w5[j], s);
    #pragma unroll
    for (int o = 16; o; o >>= 1) s += __shfl_xor_sync(0xffffffffu, s, o);
    if (lane == 0) out[b] = 1.0f / (1.0f + expf(-(s + b5[0])));
}

// ---------------- launcher --------------------------------------------------
template <typename T>
static T* sym_addr(const void* symbol)
{
    void* p = nullptr;
    cudaGetSymbolAddress(&p, symbol);
    return (T*)p;
}

extern "C" void kernel_launch(void* const* d_in, const int* in_sizes, int n_in,
                              void* d_out, int out_size)
{
    const float* Xnum = (const float*)d_in[0];
    const int*   cat  = (const int*)  d_in[1];
    const float* emb  = (const float*)d_in[2];
    const float* bw1  = (const float*)d_in[3];
    const float* bb1  = (const float*)d_in[4];
    const float* bw2  = (const float*)d_in[5];
    const float* bb2  = (const float*)d_in[6];
    const float* bw3  = (const float*)d_in[7];
    const float* bb3  = (const float*)d_in[8];
    const float* tw1  = (const float*)d_in[9];
    const float* tb1  = (const float*)d_in[10];
    const float* tw2  = (const float*)d_in[11];
    const float* tb2  = (const float*)d_in[12];
    const float* tw3  = (const float*)d_in[13];
    const float* tb3  = (const float*)d_in[14];
    const float* tw4  = (const float*)d_in[15];
    const float* tb4  = (const float*)d_in[16];
    const float* tw5  = (const float*)d_in[17];
    const float* tb5  = (const float*)d_in[18];
    float* out = (float*)d_out;

    fp16* h1 = sym_addr<fp16>(g_h1);
    fp16* h2 = sym_addr<fp16>(g_h2);
    fp16* bt = sym_addr<fp16>(g_bt);
    fp16* x  = sym_addr<fp16>(g_x);
    fp16* t1 = sym_addr<fp16>(g_t1);
    fp16* t2 = sym_addr<fp16>(g_t2);
    fp16* t3 = sym_addr<fp16>(g_t3);
    float* t4 = sym_addr<float>(g_t4);
    fp16* w2 = sym_addr<fp16>(g_w2);
    fp16* w3 = sym_addr<fp16>(g_w3);
    fp16* u1 = sym_addr<fp16>(g_u1);
    fp16* u2 = sym_addr<fp16>(g_u2);
    fp16* u3 = sym_addr<fp16>(g_u3);
    fp16* u4 = sym_addr<fp16>(g_u4);

    cudaFuncSetAttribute(gemm_tc,
                         cudaFuncAttributeMaxDynamicSharedMemorySize, GEMM_SMEM);

    // merged weight prep (1 launch)
    prep_kernel<<<(N_PREP + 255) / 256, 256>>>(bw2, bw3, tw1, tw2, tw3, tw4);

    // bottom MLP
    bottom1_kernel<<<BATCH / 32, 256>>>(Xnum, bw1, bb1);
    gemm_tc<<<dim3(2, BATCH / 128), 256, GEMM_SMEM>>>(
        h1, w2, bb2, nullptr, h2, 512, 256, 1);
    gemm_tc<<<dim3(1, BATCH / 128), 256, GEMM_SMEM>>>(
        h2, w3, bb3, nullptr, bt, 256, 128, 1);

    // gather + interactions -> x [B, 480] fp16
    interact_kernel<<<BATCH / 4, 128>>>(cat, emb);

    // top MLP (K=480 for layer 1, no padding)
    gemm_tc<<<dim3(8, BATCH / 128), 256, GEMM_SMEM>>>(
        x,  u1, tb1, nullptr, t1, XDIM, 1024, 1);
    gemm_tc<<<dim3(8, BATCH / 128), 256, GEMM_SMEM>>>(
        t1, u2, tb2, nullptr, t2, 1024, 1024, 1);
    gemm_tc<<<dim3(4, BATCH / 128), 256, GEMM_SMEM>>>(
        t2, u3, tb3, nullptr, t3, 1024, 512, 1);
    gemm_tc<<<dim3(2, BATCH / 128), 256, GEMM_SMEM>>>(
        t3, u4, tb4, t4, nullptr, 512, 256, 1);

    // final dot + sigmoid
    final_kernel<<<BATCH / 8, 256>>>(tw5, tb5, out);
}